// round 17
// baseline (speedup 1.0000x reference)
#include <cuda_runtime.h>
#include <cstdint>
#include <cstddef>

#define L     1024
#define DM    256
#define DI    512
#define DS    16
#define RK    16
#define NSEQ  4
#define ROWS  (NSEQ*L)      // 4096
#define CH    32
#define CLEN  (L/CH)        // 32

typedef unsigned long long ull;

// ---------------- device scratch ----------------
__device__ float g_a1[ROWS*DM];          // inter-layer activation
__device__ float g_xz[ROWS*2*DI];        // in_proj output (xc | z)
__device__ float g_xc[ROWS*DI];          // conv+silu output
__device__ float g_dblp[2][ROWS*48];     // x_proj partial outputs (k-split)
__device__ float g_dt[ROWS*DI];          // softplus dt (written by scan_phase1)
__device__ float g_y[ROWS*DI];           // gated scan output
__device__ float g_P[NSEQ*DI*CH*DS];     // per-chunk decay
__device__ float g_H[NSEQ*DI*CH*DS];     // per-chunk end state -> init state
__device__ float g_A2[4*DI*DS];          // precomputed -exp(A_log)*log2e

// ---------------- helpers ----------------
__device__ __forceinline__ ull pk2(float x, float y){
    ull r; asm("mov.b64 %0, {%1, %2};" : "=l"(r) : "f"(x), "f"(y)); return r;
}
__device__ __forceinline__ float2 upk2(ull v){
    float2 f; asm("mov.b64 {%0, %1}, %2;" : "=f"(f.x), "=f"(f.y) : "l"(v)); return f;
}
__device__ __forceinline__ void ffma2(ull &c, ull a, ull b){
    asm("fma.rn.f32x2 %0, %1, %2, %0;" : "+l"(c) : "l"(a), "l"(b));
}
__device__ __forceinline__ float ex2f(float x){
    float r; asm("ex2.approx.ftz.f32 %0, %1;" : "=f"(r) : "f"(x)); return r;
}
__device__ __forceinline__ float lg2f(float x){
    float r; asm("lg2.approx.ftz.f32 %0, %1;" : "=f"(r) : "f"(x)); return r;
}
#define LOG2E  1.4426950408889634f
#define RLOG2E 0.6931471805599453f
__device__ __forceinline__ float silu_f(float x){ return x / (1.f + ex2f(-LOG2E*x)); }
__device__ __forceinline__ float softplus_f(float x){
    float r = lg2f(1.f + ex2f(x*LOG2E)) * RLOG2E;
    return x > 20.f ? x : r;
}

// row remap helpers (prep / final fused into GEMM)
__device__ __forceinline__ const float* arow(const float* Abase, int asel, int rr, int K,
                                             const float* xp){
    if (asel == 3){
        int sio = rr>>10, b = sio&1, c = sio>>1, l = rr&(L-1);
        return xp + ((size_t)(b*L + (c ? (L-1-l) : l)))*DM;
    }
    return Abase + (size_t)rr*K;
}
__device__ __forceinline__ float* crow(float* Cbase, int csel, int rr, int N, float* outp){
    if (csel == 3){
        int sio = rr>>10, b = sio&1, c = sio>>1, l = rr&(L-1);
        return outp + ((size_t)(b*L + (c ? (L-1-l) : l)))*(2*DM) + c*DM;
    }
    return Cbase + (size_t)rr*N;
}

// ---------------- A2 table: -exp(A_log) * log2e ----------------
__global__ void a2_kernel(const float* __restrict__ A_log){
    int idx = blockIdx.x*blockDim.x + threadIdx.x;   // 4*DI*DS
    g_A2[idx] = -expf(A_log[idx]) * LOG2E;
}

// ============== gemm2: C[r,n] = sum_k A[r,k]*W[n,k] ==============
// BM x BN block tile, 256 threads (16x16). Row-pair f32x2 accumulators.
// Register double-buffered k-tiles; B smem PRE-PACKED as (b,b) f32x2 in a
// permuted layout: slot s holds column n=(s&15)*CN+(s>>4) -> stores 8B-apart
// per k (conflict-free), reads Bs2[k][c*16+tx] lane-consecutive (conflict-free),
// and acc[p][c] still maps to column tx*CN+c (epilogue unchanged).
// asel: 1=g_a1 2=g_y 3=x(remap) ; csel: 1=g_a1 2=g_xz 3=out(remap)
template<int BM, int BN>
__global__ __launch_bounds__(256) void gemm2(int asel, const float* __restrict__ Wall,
                                             int csel, int N, int K, int lay,
                                             const float* __restrict__ xin,
                                             float* __restrict__ outp)
{
    const float* A    = (asel==1) ? g_a1 : g_y;   // asel==3 handled in arow
    float*       Cout = (csel==1) ? g_a1 : g_xz;

    constexpr int RT  = BM/16;            // rows per thread
    constexpr int NP  = RT/2;             // row pairs per thread
    constexpr int CN  = BN/16;            // cols per thread
    constexpr int NA  = BM/64;            // A float4 loads per thread
    constexpr int NB  = BN/64;            // B float4 loads per thread
    constexpr int BST2 = BN + 2;          // Bs2 row stride (ulls)

    __shared__ float As[16*(BM+4)];
    __shared__ ull   Bs2[16*BST2];

    int tid = threadIdx.x;
    int tx  = tid & 15, ty = tid >> 4;
    int r0  = blockIdx.y*BM;
    int n0  = blockIdx.x*BN;
    int si  = r0 >> 10;
    int wl  = lay + 2*(si>>1);
    const float* W = Wall + (size_t)wl*N*K;

    ull acc[NP][CN];
    #pragma unroll
    for (int p=0;p<NP;p++)
        #pragma unroll
        for (int c=0;c<CN;c++) acc[p][c]=0ull;

    int ra = (tid>>2), ka = (tid&3)*4;
    // permuted B columns per loader slot
    int bn[NB];
    #pragma unroll
    for (int it=0; it<NB; it++){
        int s = ra + it*64;
        bn[it] = (s & 15)*CN + (s >> 4);
    }

    // prologue: load k-tile 0 into registers
    float4 pa[NA], pb[NB];
    #pragma unroll
    for (int it=0; it<NA; it++)
        pa[it] = *(const float4*)(arow(A, asel, r0+ra+it*64, K, xin) + ka);
    #pragma unroll
    for (int it=0; it<NB; it++)
        pb[it] = *(const float4*)(W + (size_t)(n0+bn[it])*K + ka);

    for (int k0=0; k0<K; k0+=16){
        // stage current tile into smem
        #pragma unroll
        for (int it=0; it<NA; it++){
            int r = ra + it*64;
            As[(ka+0)*(BM+4)+r]=pa[it].x; As[(ka+1)*(BM+4)+r]=pa[it].y;
            As[(ka+2)*(BM+4)+r]=pa[it].z; As[(ka+3)*(BM+4)+r]=pa[it].w;
        }
        #pragma unroll
        for (int it=0; it<NB; it++){
            int s = ra + it*64;
            Bs2[(ka+0)*BST2+s]=pk2(pb[it].x,pb[it].x);
            Bs2[(ka+1)*BST2+s]=pk2(pb[it].y,pb[it].y);
            Bs2[(ka+2)*BST2+s]=pk2(pb[it].z,pb[it].z);
            Bs2[(ka+3)*BST2+s]=pk2(pb[it].w,pb[it].w);
        }
        __syncthreads();
        // prefetch next k-tile (LDGs fly during compute)
        if (k0 + 16 < K){
            #pragma unroll
            for (int it=0; it<NA; it++)
                pa[it] = *(const float4*)(arow(A, asel, r0+ra+it*64, K, xin) + k0+16 + ka);
            #pragma unroll
            for (int it=0; it<NB; it++)
                pb[it] = *(const float4*)(W + (size_t)(n0+bn[it])*K + k0+16 + ka);
        }
        #pragma unroll
        for (int k=0;k<16;k++){
            const ull* ap = (const ull*)&As[k*(BM+4) + ty*RT];
            ull av[NP];
            #pragma unroll
            for (int p=0;p<NP;p++) av[p]=ap[p];
            const ull* bp = &Bs2[k*BST2 + tx];
            ull bb[CN];
            #pragma unroll
            for (int c=0;c<CN;c++) bb[c]=bp[c*16];
            #pragma unroll
            for (int c=0;c<CN;c++)
                #pragma unroll
                for (int p=0;p<NP;p++) ffma2(acc[p][c], av[p], bb[c]);
        }
        __syncthreads();
    }
    #pragma unroll
    for (int p=0;p<NP;p++){
        float lo[CN], hi[CN];
        #pragma unroll
        for (int c=0;c<CN;c++){ float2 v = upk2(acc[p][c]); lo[c]=v.x; hi[c]=v.y; }
        float* c0 = crow(Cout, csel, r0 + ty*RT + 2*p,     N, outp) + n0 + tx*CN;
        float* c1 = crow(Cout, csel, r0 + ty*RT + 2*p + 1, N, outp) + n0 + tx*CN;
        #pragma unroll
        for (int v4=0; v4<CN/4; v4++){
            ((float4*)c0)[v4] = make_float4(lo[4*v4],lo[4*v4+1],lo[4*v4+2],lo[4*v4+3]);
            ((float4*)c1)[v4] = make_float4(hi[4*v4],hi[4*v4+1],hi[4*v4+2],hi[4*v4+3]);
        }
    }
}

// ============== xproj3: fused conv+silu + dbl = xc @ Wx^T (k-split x2) ==============
__global__ __launch_bounds__(256) void xproj3(const float* __restrict__ Wx,
                                              const float* __restrict__ cw,
                                              const float* __restrict__ cb, int lay){
    __shared__ float sA[32*130];
    __shared__ float sW[48*130];

    int tid = threadIdx.x;
    int tx  = tid & 15, ty = tid >> 4;
    int r0  = blockIdx.x*32;
    int kh  = blockIdx.y;            // k half: [kh*256, kh*256+256)
    int si  = r0 >> 10;
    int wl  = lay + 2*(si>>1);
    const float* Wb  = Wx + (size_t)wl*48*DI;
    const float* cwb = cw + (size_t)wl*DI*4;
    const float* cbb = cb + (size_t)wl*DI;

    ull acc[2][3];
    #pragma unroll
    for (int i=0;i<2;i++){ acc[i][0]=0ull; acc[i][1]=0ull; acc[i][2]=0ull; }

    for (int kc=0; kc<2; kc++){
        int k0 = kh*256 + kc*128;
        #pragma unroll
        for (int it=0; it<4; it++){
            int i = tid + it*256;            // 0..1023
            int r = i>>5, q = i&31;
            int rr = r0 + r, l = rr & (L-1);
            int d0 = k0 + q*4;
            const float* xp = g_xz + (size_t)rr*(2*DI) + d0;
            float4 z4 = make_float4(0.f,0.f,0.f,0.f);
            float4 v0 = (l>=3) ? *(const float4*)(xp - 3*(2*DI)) : z4;
            float4 v1 = (l>=2) ? *(const float4*)(xp - 2*(2*DI)) : z4;
            float4 v2 = (l>=1) ? *(const float4*)(xp - 1*(2*DI)) : z4;
            float4 v3 = *(const float4*)(xp);
            float4 w0 = *(const float4*)(cwb + (size_t)d0*4);
            float4 w1 = *(const float4*)(cwb + (size_t)d0*4 + 4);
            float4 w2 = *(const float4*)(cwb + (size_t)d0*4 + 8);
            float4 w3 = *(const float4*)(cwb + (size_t)d0*4 + 12);
            float4 bb = *(const float4*)(cbb + d0);
            float s0 = bb.x + v0.x*w0.x + v1.x*w0.y + v2.x*w0.z + v3.x*w0.w;
            float s1 = bb.y + v0.y*w1.x + v1.y*w1.y + v2.y*w1.z + v3.y*w1.w;
            float s2 = bb.z + v0.z*w2.x + v1.z*w2.y + v2.z*w2.z + v3.z*w2.w;
            float s3 = bb.w + v0.w*w3.x + v1.w*w3.y + v2.w*w3.z + v3.w*w3.w;
            s0 = silu_f(s0); s1 = silu_f(s1); s2 = silu_f(s2); s3 = silu_f(s3);
            float* ap = &sA[r*130 + q*4];
            ap[0]=s0; ap[1]=s1; ap[2]=s2; ap[3]=s3;
            *(float4*)(g_xc + (size_t)rr*DI + d0) = make_float4(s0,s1,s2,s3);
        }
        #pragma unroll
        for (int it=0; it<6; it++){
            int i = tid + it*256;            // 0..1535
            int j = i>>5, q = i&31;
            float4 v = *(const float4*)(Wb + (size_t)j*DI + k0 + q*4);
            float* wp = &sW[j*130 + q*4];
            wp[0]=v.x; wp[1]=v.y; wp[2]=v.z; wp[3]=v.w;
        }
        __syncthreads();
        const ull* a0p = (const ull*)&sA[(ty*2  )*130];
        const ull* a1p = (const ull*)&sA[(ty*2+1)*130];
        const ull* w0p = (const ull*)&sW[(tx    )*130];
        const ull* w1p = (const ull*)&sW[(tx+16 )*130];
        const ull* w2p = (const ull*)&sW[(tx+32 )*130];
        #pragma unroll 8
        for (int k2=0;k2<64;k2++){
            ull a0=a0p[k2], a1=a1p[k2];
            ull b0=w0p[k2], b1=w1p[k2], b2=w2p[k2];
            ffma2(acc[0][0],a0,b0); ffma2(acc[0][1],a0,b1); ffma2(acc[0][2],a0,b2);
            ffma2(acc[1][0],a1,b0); ffma2(acc[1][1],a1,b1); ffma2(acc[1][2],a1,b2);
        }
        __syncthreads();
    }
    #pragma unroll
    for (int i=0;i<2;i++){
        int rr = r0 + ty*2 + i;
        float* dp = g_dblp[kh] + (size_t)rr*48;
        float2 v0=upk2(acc[i][0]), v1=upk2(acc[i][1]), v2=upk2(acc[i][2]);
        dp[tx]    = v0.x+v0.y;
        dp[tx+16] = v1.x+v1.y;
        dp[tx+32] = v2.x+v2.y;
    }
}

// ---------------- scan phase 1 (256 thr, s-split x2) + fused dt computation ----------------
// Computes dt = softplus(dtr @ Wdt^T + b) for its (CLEN rows x 128 d) tile in the
// prologue, uses it, and writes g_dt for scan_phase2.
__global__ __launch_bounds__(256) void scan_phase1(const float* __restrict__ Wdt,
                                                   const float* __restrict__ bdt, int lay){
    int tid = threadIdx.x;
    int dl  = tid & 127;
    int sh  = tid >> 7;
    int d0b = blockIdx.x*128;
    int d   = d0b + dl;
    int ch  = blockIdx.y;
    int si  = blockIdx.z;
    int wl  = lay + 2*(si>>1);
    __shared__ float sdt[CLEN][128];
    __shared__ float sxc[CLEN][128];
    __shared__ float sB[CLEN][DS];
    __shared__ float sdr[CLEN][DS];      // dt_raw (sum of k-split partials)
    int rbase = si*L + ch*CLEN;
    // xc tile: CLEN*32 float4, 4 per thread
    #pragma unroll
    for (int it=0; it<CLEN/8; it++){
        int i  = tid + it*256;
        int ll = i >> 5, dd = (i & 31)*4;
        *(float4*)&sxc[ll][dd] = *(const float4*)(g_xc + (size_t)(rbase+ll)*DI + d0b + dd);
    }
    #pragma unroll
    for (int i=tid; i<CLEN*DS; i+=256){
        int ll = i>>4, s = i&15;
        size_t off = (size_t)(rbase+ll)*48 + s;
        sdr[ll][s] = g_dblp[0][off]    + g_dblp[1][off];       // dt_raw
        sB[ll][s]  = g_dblp[0][off+16] + g_dblp[1][off+16];    // B
    }
    // per-thread dt weights (both sh halves load same row -> L2 broadcast)
    float wdt[16];
    {
        const float4* wp = (const float4*)(Wdt + (size_t)(wl*DI + d)*RK);
        #pragma unroll
        for (int q=0;q<4;q++){
            float4 v = wp[q];
            wdt[4*q+0]=v.x; wdt[4*q+1]=v.y; wdt[4*q+2]=v.z; wdt[4*q+3]=v.w;
        }
    }
    float bias = bdt[wl*DI + d];
    __syncthreads();
    // compute dt for rows [sh*16, sh*16+16), write smem + g_dt
    #pragma unroll
    for (int lr=0; lr<CLEN/2; lr++){
        int ll = sh*(CLEN/2) + lr;
        float acc = bias;
        #pragma unroll
        for (int q=0;q<16;q++) acc = fmaf(sdr[ll][q], wdt[q], acc);
        float dtv = softplus_f(acc);
        sdt[ll][dl] = dtv;
        g_dt[(size_t)(rbase+ll)*DI + d] = dtv;
    }
    __syncthreads();
    float A2[8], h[8];
    {
        const float4* ap = (const float4*)(g_A2 + (size_t)(wl*DI+d)*DS + sh*8);
        float4 v0 = ap[0], v1 = ap[1];
        A2[0]=v0.x; A2[1]=v0.y; A2[2]=v0.z; A2[3]=v0.w;
        A2[4]=v1.x; A2[5]=v1.y; A2[6]=v1.z; A2[7]=v1.w;
    }
    #pragma unroll
    for (int s=0;s<8;s++) h[s]=0.f;
    float sdtacc = 0.f;
    #pragma unroll 4
    for (int ll=0; ll<CLEN; ll++){
        float dtc = sdt[ll][dl];
        float xcv = sxc[ll][dl];
        float dtx = dtc*xcv;
        sdtacc += dtc;
        #pragma unroll
        for (int s=0;s<8;s++){
            float dA = ex2f(dtc*A2[s]);
            h[s] = fmaf(dA, h[s], dtx*sB[ll][sh*8+s]);
        }
    }
    size_t ob = ((size_t)(si*DI + d)*CH + ch)*DS + sh*8;
    float P[8];
    #pragma unroll
    for (int s=0;s<8;s++) P[s] = ex2f(sdtacc*A2[s]);
    *(float4*)(g_H+ob)   = make_float4(h[0],h[1],h[2],h[3]);
    *(float4*)(g_H+ob+4) = make_float4(h[4],h[5],h[6],h[7]);
    *(float4*)(g_P+ob)   = make_float4(P[0],P[1],P[2],P[3]);
    *(float4*)(g_P+ob+4) = make_float4(P[4],P[5],P[6],P[7]);
}

// ---------------- scan combine ----------------
__global__ void scan_comb(){
    int idx = blockIdx.x*blockDim.x + threadIdx.x;
    int s = idx & 15;
    int t = idx >> 4;
    size_t base = (size_t)t*CH*DS + s;
    float run = 0.f;
    #pragma unroll 8
    for (int c=0;c<CH;c++){
        size_t p = base + (size_t)c*DS;
        float he = g_H[p], pe = g_P[p];
        g_H[p] = run;
        run = fmaf(pe, run, he);
    }
}

// ---------------- scan phase 2 (256 thr, s-split in-warp) ----------------
__global__ __launch_bounds__(256) void scan_phase2(const float* __restrict__ Dp, int lay){
    int tid  = threadIdx.x;
    int w    = tid >> 5, lane = tid & 31;
    int sh   = lane >> 4;
    int dl   = w*16 + (lane & 15);
    int d0b  = blockIdx.x*128;
    int d    = d0b + dl;
    int ch   = blockIdx.y;
    int si   = blockIdx.z;
    int wl   = lay + 2*(si>>1);
    __shared__ float sdt[CLEN][128];
    __shared__ float sxc[CLEN][128];
    __shared__ float sB[CLEN][DS];
    __shared__ float sC[CLEN][DS];
    int rbase = si*L + ch*CLEN;
    #pragma unroll
    for (int it=0; it<CLEN/8; it++){
        int i  = tid + it*256;
        int ll = i >> 5, dd = (i & 31)*4;
        *(float4*)&sdt[ll][dd] = *(const float4*)(g_dt + (size_t)(rbase+ll)*DI + d0b + dd);
        *(float4*)&sxc[ll][dd] = *(const float4*)(g_xc + (size_t)(rbase+ll)*DI + d0b + dd);
    }
    #pragma unroll
    for (int i=tid; i<CLEN*DS; i+=256){
        int ll = i>>4, s = i&15;
        size_t off = (size_t)(rbase+ll)*48 + 16 + s;
        sB[ll][s] = g_dblp[0][off]    + g_dblp[1][off];
        sC[ll][s] = g_dblp[0][off+16] + g_dblp[1][off+16];
    }
    __syncthreads();
    float A2[8], h[8];
    size_t ib = ((size_t)(si*DI + d)*CH + ch)*DS + sh*8;
    {
        const float4* ap = (const float4*)(g_A2 + (size_t)(wl*DI+d)*DS + sh*8);
        float4 v0 = ap[0], v1 = ap[1];
        A2[0]=v0.x; A2[1]=v0.y; A2[2]=v0.z; A2[3]=v0.w;
        A2[4]=v1.x; A2[5]=v1.y; A2[6]=v1.z; A2[7]=v1.w;
        float4 h0 = *(const float4*)(g_H+ib);
        float4 h1 = *(const float4*)(g_H+ib+4);
        h[0]=h0.x; h[1]=h0.y; h[2]=h0.z; h[3]=h0.w;
        h[4]=h1.x; h[5]=h1.y; h[6]=h1.z; h[7]=h1.w;
    }
    float Dd = Dp[wl*DI + d];
    #pragma unroll 4
    for (int ll=0; ll<CLEN; ll++){
        int r = rbase + ll;
        float dtc = sdt[ll][dl];
        float xcv = sxc[ll][dl];
        float z   = g_xz[(size_t)r*(2*DI) + DI + d];
        float dtx = dtc*xcv;
        float y0=0.f, y1=0.f;
        #pragma unroll
        for (int s=0;s<8;s++){
            float dA = ex2f(dtc*A2[s]);
            h[s] = fmaf(dA, h[s], dtx*sB[ll][sh*8+s]);
            if (s & 1) y1 = fmaf(h[s], sC[ll][sh*8+s], y1);
            else       y0 = fmaf(h[s], sC[ll][sh*8+s], y0);
        }
        float yp = y0 + y1;
        float y  = yp + __shfl_xor_sync(0xffffffffu, yp, 16);
        if (sh == 0){
            y = fmaf(xcv, Dd, y);
            y *= silu_f(z);
            g_y[(size_t)r*DI + d] = y;
        }
    }
}

// ---------------- launch ----------------
extern "C" void kernel_launch(void* const* d_in, const int* in_sizes, int n_in,
                              void* d_out, int out_size)
{
    (void)in_sizes; (void)n_in; (void)out_size;
    const float* x        = (const float*)d_in[0];
    const float* in_proj  = (const float*)d_in[1];
    const float* conv_w   = (const float*)d_in[2];
    const float* conv_b   = (const float*)d_in[3];
    const float* x_proj   = (const float*)d_in[4];
    const float* dt_proj  = (const float*)d_in[5];
    const float* dt_bias  = (const float*)d_in[6];
    const float* A_log    = (const float*)d_in[7];
    const float* Dp       = (const float*)d_in[8];
    const float* out_proj = (const float*)d_in[9];
    float* out = (float*)d_out;

    a2_kernel<<<4*DI*DS/256, 256>>>(A_log);

    for (int lay = 0; lay < 2; lay++){
        int ain  = lay ? 1 : 3;        // layer0 reads x with prep-remap, layer1 reads g_a1
        int cout = lay ? 3 : 1;        // layer1 writes out with final-remap, layer0 -> g_a1

        // xz = act @ in_proj^T   (N=1024, K=256), 128x128 tiles
        gemm2<128,128><<<dim3((2*DI)/128, ROWS/128), 256>>>(ain, in_proj, 2, 2*DI, DM, lay, x, nullptr);
        xproj3<<<dim3(ROWS/32, 2), 256>>>(x_proj, conv_w, conv_b, lay);
        scan_phase1<<<dim3(DI/128, CH, NSEQ), 256>>>(dt_proj, dt_bias, lay);
        scan_comb<<<NSEQ*DI*DS/256, 256>>>();
        scan_phase2<<<dim3(DI/128, CH, NSEQ), 256>>>(Dp, lay);
        // act_out = y @ out_proj^T  (N=256, K=512), 64x64 tiles
        gemm2<64,64><<<dim3(DM/64, ROWS/64), 256>>>(2, out_proj, cout, DM, DI, lay, nullptr, out);
    }
}